// round 6
// baseline (speedup 1.0000x reference)
#include <cuda_runtime.h>
#include <math.h>

#define TQ 256
#define BQ 1024
#define DQ 64
#define HQ 32

// Scratch (no runtime allocation allowed)
__device__ float g_xt[TQ * BQ * HQ];                  // conv output, [t][b][o]
__device__ __align__(16) float g_w0t[192 * 32];       // vec4 layout, see prep
__device__ __align__(16) float g_w1t[96 * 32];
__device__ __align__(16) float g_w2t[96 * 32];
__device__ float g_hs[BQ * HQ];                       // persisted h between rec kernels
__device__ float g_cs[BQ * HQ];                       // persisted c

__device__ __forceinline__ float rcp_(float x) {
    float r; asm("rcp.approx.f32 %0, %1;" : "=f"(r) : "f"(x)); return r;
}
__device__ __forceinline__ float sigm_(float x) {
    return rcp_(1.0f + __expf(-x));
}
__device__ __forceinline__ float tanh_(float x) {
    return 1.0f - 2.0f * rcp_(1.0f + __expf(2.0f * x));
}
__device__ __forceinline__ float sigmoid_acc(float x) {
    return 1.0f / (1.0f + expf(-x));
}
__device__ __forceinline__ void fma2_(unsigned long long& acc,
                                      unsigned long long a,
                                      unsigned long long b) {
    asm("fma.rn.f32x2 %0, %1, %2, %3;" : "=l"(acc) : "l"(a), "l"(b), "l"(acc));
}
__device__ __forceinline__ float unpack_add_(unsigned long long acc) {
    float lo, hi;
    asm("mov.b64 {%0, %1}, %2;" : "=f"(lo), "=f"(hi) : "l"(acc));
    return lo + hi;
}
__device__ __forceinline__ unsigned long long pack2_(float lo, float hi) {
    unsigned long long r;
    asm("mov.b64 %0, {%1, %2};" : "=l"(r) : "f"(lo), "f"(hi));
    return r;
}

// ---------------------------------------------------------------------------
// Kernel 0: repack conv weights (unchanged).
// ---------------------------------------------------------------------------
__global__ void prep_kernel(const float* __restrict__ w0,
                            const float* __restrict__ w1,
                            const float* __restrict__ w2) {
    int i = threadIdx.x + blockIdx.x * 256;
    if (i < 6144) {
        int jj = i & 3, o = (i >> 2) & 31, kd4 = i >> 7;
        int k = kd4 >> 4, d4 = kd4 & 15;
        g_w0t[i] = w0[o * 192 + (4 * d4 + jj) * 3 + k];
    }
    if (i < 3072) {
        int jj = i & 3, o = (i >> 2) & 31, ki4 = i >> 7;
        int k = ki4 >> 3, i4 = ki4 & 7;
        g_w1t[i] = w1[o * 96 + (4 * i4 + jj) * 3 + k];
        g_w2t[i] = w2[o * 96 + (4 * i4 + jj) * 3 + k];
    }
}

// ---------------------------------------------------------------------------
// Kernel 1: fused 3-layer TCN with packed f32x2 FMAs (unchanged from R4).
// ---------------------------------------------------------------------------
__global__ __launch_bounds__(256, 2) void conv_fused_kernel(
    const float* __restrict__ x,
    const float* __restrict__ b0, const float* __restrict__ b1,
    const float* __restrict__ b2) {
    __shared__ __align__(16) float xs[70 * 64];
    __shared__ __align__(16) float s1[72 * 32];
    __shared__ __align__(16) float s2[68 * 32];
    const ulonglong2* xs2 = (const ulonglong2*)xs;
    const ulonglong2* s1v = (const ulonglong2*)s1;
    const ulonglong2* s2v = (const ulonglong2*)s2;

    const int tid = threadIdx.x;
    const int b = blockIdx.x >> 2;
    const int t0 = (blockIdx.x & 3) * 64;

    for (int i = tid; i < 70 * 64; i += 256) {
        int r = i >> 6, d = i & 63, t = t0 - 3 + r;
        xs[i] = (t >= 0 && t < TQ) ? x[b * TQ * DQ + t * DQ + d] : 0.0f;
    }
    if (tid < 128) s1[68 * 32 + tid] = 0.0f;
    if (tid < 64)  s2[66 * 32 + tid] = 0.0f;
    __syncthreads();

    const int w = tid >> 5, o = tid & 31;
    const ulonglong2* wp0 = (const ulonglong2*)g_w0t;
    const ulonglong2* wp1 = (const ulonglong2*)g_w1t;
    const ulonglong2* wp2 = (const ulonglong2*)g_w2t;

    for (int c = w; c < 17; c += 8) {
        const int base = c << 2;
        unsigned long long a0 = 0ull, a1 = 0ull, a2 = 0ull, a3 = 0ull;
        #pragma unroll 4
        for (int d4 = 0; d4 < 16; d4++) {
            ulonglong2 w0k = __ldg(&wp0[d4 * 32 + o]);
            ulonglong2 w1k = __ldg(&wp0[(16 + d4) * 32 + o]);
            ulonglong2 w2k = __ldg(&wp0[(32 + d4) * 32 + o]);
            ulonglong2 r0 = xs2[(base + 0) * 16 + d4];
            ulonglong2 r1 = xs2[(base + 1) * 16 + d4];
            ulonglong2 r2 = xs2[(base + 2) * 16 + d4];
            ulonglong2 r3 = xs2[(base + 3) * 16 + d4];
            ulonglong2 r4 = xs2[(base + 4) * 16 + d4];
            ulonglong2 r5 = xs2[(base + 5) * 16 + d4];
            fma2_(a0, w0k.x, r0.x); fma2_(a0, w0k.y, r0.y);
            fma2_(a0, w1k.x, r1.x); fma2_(a0, w1k.y, r1.y);
            fma2_(a0, w2k.x, r2.x); fma2_(a0, w2k.y, r2.y);
            fma2_(a1, w0k.x, r1.x); fma2_(a1, w0k.y, r1.y);
            fma2_(a1, w1k.x, r2.x); fma2_(a1, w1k.y, r2.y);
            fma2_(a1, w2k.x, r3.x); fma2_(a1, w2k.y, r3.y);
            fma2_(a2, w0k.x, r2.x); fma2_(a2, w0k.y, r2.y);
            fma2_(a2, w1k.x, r3.x); fma2_(a2, w1k.y, r3.y);
            fma2_(a2, w2k.x, r4.x); fma2_(a2, w2k.y, r4.y);
            fma2_(a3, w0k.x, r3.x); fma2_(a3, w0k.y, r3.y);
            fma2_(a3, w1k.x, r4.x); fma2_(a3, w1k.y, r4.y);
            fma2_(a3, w2k.x, r5.x); fma2_(a3, w2k.y, r5.y);
        }
        float bz = __ldg(&b0[o]);
        float av[4] = {unpack_add_(a0) + bz, unpack_add_(a1) + bz,
                       unpack_add_(a2) + bz, unpack_add_(a3) + bz};
        #pragma unroll
        for (int jj = 0; jj < 4; jj++) {
            int r = base + jj, tt = t0 - 2 + r;
            float v = fmaxf(av[jj], 0.0f);
            if (tt < 0 || tt >= TQ) v = 0.0f;
            s1[r * 32 + o] = v;
        }
    }
    __syncthreads();

    for (int c = w; c < 17; c += 8) {
        const int base = c << 2;
        unsigned long long a0 = 0ull, a1 = 0ull, a2 = 0ull, a3 = 0ull;
        #pragma unroll
        for (int d4 = 0; d4 < 8; d4++) {
            ulonglong2 w0k = __ldg(&wp1[d4 * 32 + o]);
            ulonglong2 w1k = __ldg(&wp1[(8 + d4) * 32 + o]);
            ulonglong2 w2k = __ldg(&wp1[(16 + d4) * 32 + o]);
            ulonglong2 r0 = s1v[(base + 0) * 8 + d4];
            ulonglong2 r1 = s1v[(base + 1) * 8 + d4];
            ulonglong2 r2 = s1v[(base + 2) * 8 + d4];
            ulonglong2 r3 = s1v[(base + 3) * 8 + d4];
            ulonglong2 r4 = s1v[(base + 4) * 8 + d4];
            ulonglong2 r5 = s1v[(base + 5) * 8 + d4];
            fma2_(a0, w0k.x, r0.x); fma2_(a0, w0k.y, r0.y);
            fma2_(a0, w1k.x, r1.x); fma2_(a0, w1k.y, r1.y);
            fma2_(a0, w2k.x, r2.x); fma2_(a0, w2k.y, r2.y);
            fma2_(a1, w0k.x, r1.x); fma2_(a1, w0k.y, r1.y);
            fma2_(a1, w1k.x, r2.x); fma2_(a1, w1k.y, r2.y);
            fma2_(a1, w2k.x, r3.x); fma2_(a1, w2k.y, r3.y);
            fma2_(a2, w0k.x, r2.x); fma2_(a2, w0k.y, r2.y);
            fma2_(a2, w1k.x, r3.x); fma2_(a2, w1k.y, r3.y);
            fma2_(a2, w2k.x, r4.x); fma2_(a2, w2k.y, r4.y);
            fma2_(a3, w0k.x, r3.x); fma2_(a3, w0k.y, r3.y);
            fma2_(a3, w1k.x, r4.x); fma2_(a3, w1k.y, r4.y);
            fma2_(a3, w2k.x, r5.x); fma2_(a3, w2k.y, r5.y);
        }
        float bz = __ldg(&b1[o]);
        float av[4] = {unpack_add_(a0) + bz, unpack_add_(a1) + bz,
                       unpack_add_(a2) + bz, unpack_add_(a3) + bz};
        #pragma unroll
        for (int jj = 0; jj < 4; jj++) {
            int r = base + jj;
            if (r < 66) {
                int tt = t0 - 1 + r;
                float v = fmaxf(av[jj], 0.0f);
                if (tt < 0 || tt >= TQ) v = 0.0f;
                s2[r * 32 + o] = v;
            }
        }
    }
    __syncthreads();

    for (int c = w; c < 16; c += 8) {
        const int base = c << 2;
        unsigned long long a0 = 0ull, a1 = 0ull, a2 = 0ull, a3 = 0ull;
        #pragma unroll
        for (int d4 = 0; d4 < 8; d4++) {
            ulonglong2 w0k = __ldg(&wp2[d4 * 32 + o]);
            ulonglong2 w1k = __ldg(&wp2[(8 + d4) * 32 + o]);
            ulonglong2 w2k = __ldg(&wp2[(16 + d4) * 32 + o]);
            ulonglong2 r0 = s2v[(base + 0) * 8 + d4];
            ulonglong2 r1 = s2v[(base + 1) * 8 + d4];
            ulonglong2 r2 = s2v[(base + 2) * 8 + d4];
            ulonglong2 r3 = s2v[(base + 3) * 8 + d4];
            ulonglong2 r4 = s2v[(base + 4) * 8 + d4];
            ulonglong2 r5 = s2v[(base + 5) * 8 + d4];
            fma2_(a0, w0k.x, r0.x); fma2_(a0, w0k.y, r0.y);
            fma2_(a0, w1k.x, r1.x); fma2_(a0, w1k.y, r1.y);
            fma2_(a0, w2k.x, r2.x); fma2_(a0, w2k.y, r2.y);
            fma2_(a1, w0k.x, r1.x); fma2_(a1, w0k.y, r1.y);
            fma2_(a1, w1k.x, r2.x); fma2_(a1, w1k.y, r2.y);
            fma2_(a1, w2k.x, r3.x); fma2_(a1, w2k.y, r3.y);
            fma2_(a2, w0k.x, r2.x); fma2_(a2, w0k.y, r2.y);
            fma2_(a2, w1k.x, r3.x); fma2_(a2, w1k.y, r3.y);
            fma2_(a2, w2k.x, r4.x); fma2_(a2, w2k.y, r4.y);
            fma2_(a3, w0k.x, r3.x); fma2_(a3, w0k.y, r3.y);
            fma2_(a3, w1k.x, r4.x); fma2_(a3, w1k.y, r4.y);
            fma2_(a3, w2k.x, r5.x); fma2_(a3, w2k.y, r5.y);
        }
        float bz = __ldg(&b2[o]);
        const int t = t0 + base;
        g_xt[(t + 0) * (BQ * HQ) + b * HQ + o] = fmaxf(unpack_add_(a0) + bz, 0.0f);
        g_xt[(t + 1) * (BQ * HQ) + b * HQ + o] = fmaxf(unpack_add_(a1) + bz, 0.0f);
        g_xt[(t + 2) * (BQ * HQ) + b * HQ + o] = fmaxf(unpack_add_(a2) + bz, 0.0f);
        g_xt[(t + 3) * (BQ * HQ) + b * HQ + o] = fmaxf(unpack_add_(a3) + bz, 0.0f);
    }
}

// ---------------------------------------------------------------------------
// Kernel 2: recurrent scan over [TSTART, TEND).
// Matvec: k-pair packed weights (no per-iter MOVs), batch-major activations.
// Quantum: paired RY gates (q1,q2) and (q3,q4) with precomputed lane coefs.
// ---------------------------------------------------------------------------
template <int TSTART, int TEND>
__global__ __launch_bounds__(256, 1) void recurrent_kernel(
    const float* __restrict__ Wih, const float* __restrict__ Whh,
    const float* __restrict__ bih, const float* __restrict__ bhh,
    const float* __restrict__ qweights,
    const float* __restrict__ Wfc, const float* __restrict__ bfc,
    const float* __restrict__ Wout, const float* __restrict__ boutp,
    float* __restrict__ out) {
    __shared__ __align__(16) float xhf[2][256];     // [half][b*64 + idx]
    __shared__ float gsm[2][128 * 5];               // [half][j*5 + bb]
    __shared__ float qc[18], qs[18];

    const unsigned FULL = 0xffffffffu;
    const int tid = threadIdx.x;
    const int l = tid & 31;
    const int wrp = tid >> 5;
    const int half = tid >> 7;
    const int wb = wrp & 3;
    const int bglob = blockIdx.x * 8 + wrp;
    const int j = tid & 127;
    const int barid = half + 1;

    // ---- pack weight column j as adjacent-k pairs (32 u64 = 64 regs) ----
    unsigned long long wpk[32];
    #pragma unroll
    for (int p = 0; p < 16; p++)
        wpk[p] = pack2_(Wih[j * 32 + 2 * p], Wih[j * 32 + 2 * p + 1]);
    #pragma unroll
    for (int p = 0; p < 16; p++)
        wpk[16 + p] = pack2_(Whh[j * 32 + 2 * p], Whh[j * 32 + 2 * p + 1]);
    const float biasj = bih[j] + bhh[j];

    if (tid < 18) {
        float a = 0.5f * qweights[tid];
        qc[tid] = cosf(a);
        qs[tid] = sinf(a);
    }

    const float wfc0 = Wfc[l * 6 + 0], wfc1 = Wfc[l * 6 + 1], wfc2 = Wfc[l * 6 + 2];
    const float wfc3 = Wfc[l * 6 + 3], wfc4 = Wfc[l * 6 + 4], wfc5 = Wfc[l * 6 + 5];
    const float bfcl = bfc[l];
    const float woutl = Wout[l];
    const int s0cn = ((l ^ (l >> 1)) & 0x0F) | ((((l >> 4) ^ l) & 1) << 4);
    const int s1cn = s0cn ^ 16;
    const bool flipc = (l & 1) != 0;

    __syncthreads();   // qc/qs visible

    // ---- precompute per-lane paired-RY coefficients (angles are fixed) ----
    float c0a[3], s0a[3];
    float cA[3], tA1[3], tA2[3], tA3[3];
    float cB[3], tB1[3], tB2[3], tB3[3];
    float c5a[3], s5a[3];
    #pragma unroll
    for (int lay = 0; lay < 3; lay++) {
        const int b6 = lay * 6;
        c0a[lay] = qc[b6 + 0]; s0a[lay] = qs[b6 + 0];
        float c1 = qc[b6 + 1], s1 = qs[b6 + 1];
        float c2 = qc[b6 + 2], s2 = qs[b6 + 2];
        float g1 = (l & 16) ? s1 : -s1;
        float g2 = (l & 8) ? s2 : -s2;
        cA[lay] = c1 * c2; tA1[lay] = c2 * g1; tA2[lay] = c1 * g2; tA3[lay] = g1 * g2;
        float c3 = qc[b6 + 3], s3 = qs[b6 + 3];
        float c4 = qc[b6 + 4], s4 = qs[b6 + 4];
        float g3 = (l & 4) ? s3 : -s3;
        float g4 = (l & 2) ? s4 : -s4;
        cB[lay] = c3 * c4; tB1[lay] = c4 * g3; tB2[lay] = c3 * g4; tB3[lay] = g3 * g4;
        c5a[lay] = qc[b6 + 5];
        s5a[lay] = (l & 1) ? qs[b6 + 5] : -qs[b6 + 5];
    }

    float h, c;
    if (TSTART == 0) {
        h = 0.0f; c = 0.0f;
    } else {
        h = g_hs[bglob * HQ + l];
        c = g_cs[bglob * HQ + l];
    }

    float xt = g_xt[TSTART * (BQ * HQ) + bglob * HQ + l];

    for (int t = TSTART; t < TEND; t++) {
        // ---- stage activations batch-major: [b*64 + k] ----
        xhf[half][wb * 64 + l] = xt;
        xhf[half][wb * 64 + 32 + l] = h;
        asm volatile("bar.sync %0, 128;" :: "r"(barid) : "memory");

        float xt_next = 0.0f;
        if (t + 1 < TQ) xt_next = g_xt[(t + 1) * (BQ * HQ) + bglob * HQ + l];

        // ---- matvec: acc lanes hold even/odd-k partial sums ----
        {
            unsigned long long a0 = 0ull, a1 = 0ull, a2 = 0ull, a3 = 0ull;
            const ulonglong2* xv = (const ulonglong2*)&xhf[half][0];
            #pragma unroll
            for (int kg = 0; kg < 16; kg++) {
                ulonglong2 x0 = xv[kg];
                ulonglong2 x1 = xv[16 + kg];
                ulonglong2 x2 = xv[32 + kg];
                ulonglong2 x3 = xv[48 + kg];
                fma2_(a0, wpk[2 * kg], x0.x); fma2_(a0, wpk[2 * kg + 1], x0.y);
                fma2_(a1, wpk[2 * kg], x1.x); fma2_(a1, wpk[2 * kg + 1], x1.y);
                fma2_(a2, wpk[2 * kg], x2.x); fma2_(a2, wpk[2 * kg + 1], x2.y);
                fma2_(a3, wpk[2 * kg], x3.x); fma2_(a3, wpk[2 * kg + 1], x3.y);
            }
            gsm[half][j * 5 + 0] = unpack_add_(a0) + biasj;
            gsm[half][j * 5 + 1] = unpack_add_(a1) + biasj;
            gsm[half][j * 5 + 2] = unpack_add_(a2) + biasj;
            gsm[half][j * 5 + 3] = unpack_add_(a3) + biasj;
        }
        asm volatile("bar.sync %0, 128;" :: "r"(barid) : "memory");

        // ---- LSTM cell + chaotic maps ----
        float gi = gsm[half][l * 5 + wb];
        float gf = gsm[half][(l + 32) * 5 + wb];
        float gg = gsm[half][(l + 64) * 5 + wb];
        float go = gsm[half][(l + 96) * 5 + wb];
        c = sigm_(gf) * c + sigm_(gi) * tanh_(gg);
        h = sigm_(go) * tanh_(c);
        h = 3.99f * h * (1.0f - h);
        float x0h = __shfl_sync(FULL, h, 0);
        float y0h = __shfl_sync(FULL, h, 1);
        if (l == 0) h = 1.0f - 1.4f * (x0h * x0h) + y0h;
        if (l == 1) h = 0.3f * x0h;

        // ---- 6-qubit circuit ----
        float ang = (l < 6) ? 0.5f * h : 0.0f;
        float ssin, scos;
        __sincosf(ang, &ssin, &scos);
        float cs[6], sn[6];
        #pragma unroll
        for (int q = 0; q < 6; q++) {
            cs[q] = __shfl_sync(FULL, scos, q);
            sn[q] = __shfl_sync(FULL, ssin, q);
        }
        float p0r[6], p0i[6], p1r[6], p1i[6];
        #pragma unroll
        for (int i = 0; i < 6; i++) {
            const int i1 = (i + 1) % 6, i2 = (i + 2) % 6;
            float cx = cs[i], sx = sn[i];
            float cy = cs[i1], sy = sn[i1];
            float cz = cs[i2], sz = sn[i2];
            float ur = cy * cx, ui = sy * sx;
            float vr = sy * cx, vi = -(cy * sx);
            p0r[i] = ur * cz + ui * sz;
            p0i[i] = ui * cz - ur * sz;
            p1r[i] = vr * cz - vi * sz;
            p1i[i] = vi * cz + vr * sz;
        }
        float cr = 1.0f, cii = 0.0f;
        #pragma unroll
        for (int q = 1; q < 6; q++) {
            int bit = (l >> (5 - q)) & 1;
            float fr = bit ? p1r[q] : p0r[q];
            float fi = bit ? p1i[q] : p0i[q];
            float nr = cr * fr - cii * fi;
            float ni = cr * fi + cii * fr;
            cr = nr; cii = ni;
        }
        float a0r = cr * p0r[0] - cii * p0i[0];
        float a0i = cr * p0i[0] + cii * p0r[0];
        float a1r = cr * p1r[0] - cii * p1i[0];
        float a1i = cr * p1i[0] + cii * p1r[0];

        #pragma unroll
        for (int lay = 0; lay < 3; lay++) {
            {   // RY q=0 (register pair, no shfl)
                float cg = c0a[lay], sg = s0a[lay];
                float n0r = cg * a0r - sg * a1r, n0i = cg * a0i - sg * a1i;
                float n1r = sg * a0r + cg * a1r, n1i = sg * a0i + cg * a1i;
                a0r = n0r; a0i = n0i; a1r = n1r; a1i = n1i;
            }
            // paired RY(q1,q2): masks 16, 8, 24
            {
                float ka = cA[lay], k1 = tA1[lay], k2 = tA2[lay], k3 = tA3[lay];
                float v16, v8, v24;
                v16 = __shfl_xor_sync(FULL, a0r, 16);
                v8  = __shfl_xor_sync(FULL, a0r, 8);
                v24 = __shfl_xor_sync(FULL, a0r, 24);
                a0r = fmaf(k3, v24, fmaf(k2, v8, fmaf(k1, v16, ka * a0r)));
                v16 = __shfl_xor_sync(FULL, a0i, 16);
                v8  = __shfl_xor_sync(FULL, a0i, 8);
                v24 = __shfl_xor_sync(FULL, a0i, 24);
                a0i = fmaf(k3, v24, fmaf(k2, v8, fmaf(k1, v16, ka * a0i)));
                v16 = __shfl_xor_sync(FULL, a1r, 16);
                v8  = __shfl_xor_sync(FULL, a1r, 8);
                v24 = __shfl_xor_sync(FULL, a1r, 24);
                a1r = fmaf(k3, v24, fmaf(k2, v8, fmaf(k1, v16, ka * a1r)));
                v16 = __shfl_xor_sync(FULL, a1i, 16);
                v8  = __shfl_xor_sync(FULL, a1i, 8);
                v24 = __shfl_xor_sync(FULL, a1i, 24);
                a1i = fmaf(k3, v24, fmaf(k2, v8, fmaf(k1, v16, ka * a1i)));
            }
            // paired RY(q3,q4): masks 4, 2, 6
            {
                float kb = cB[lay], k1 = tB1[lay], k2 = tB2[lay], k3 = tB3[lay];
                float v4, v2, v6;
                v4 = __shfl_xor_sync(FULL, a0r, 4);
                v2 = __shfl_xor_sync(FULL, a0r, 2);
                v6 = __shfl_xor_sync(FULL, a0r, 6);
                a0r = fmaf(k3, v6, fmaf(k2, v2, fmaf(k1, v4, kb * a0r)));
                v4 = __shfl_xor_sync(FULL, a0i, 4);
                v2 = __shfl_xor_sync(FULL, a0i, 2);
                v6 = __shfl_xor_sync(FULL, a0i, 6);
                a0i = fmaf(k3, v6, fmaf(k2, v2, fmaf(k1, v4, kb * a0i)));
                v4 = __shfl_xor_sync(FULL, a1r, 4);
                v2 = __shfl_xor_sync(FULL, a1r, 2);
                v6 = __shfl_xor_sync(FULL, a1r, 6);
                a1r = fmaf(k3, v6, fmaf(k2, v2, fmaf(k1, v4, kb * a1r)));
                v4 = __shfl_xor_sync(FULL, a1i, 4);
                v2 = __shfl_xor_sync(FULL, a1i, 2);
                v6 = __shfl_xor_sync(FULL, a1i, 6);
                a1i = fmaf(k3, v6, fmaf(k2, v2, fmaf(k1, v4, kb * a1i)));
            }
            // RY q=5 (mask 1)
            {
                float cg = c5a[lay], sg = s5a[lay];
                float o0r = __shfl_xor_sync(FULL, a0r, 1);
                float o0i = __shfl_xor_sync(FULL, a0i, 1);
                float o1r = __shfl_xor_sync(FULL, a1r, 1);
                float o1i = __shfl_xor_sync(FULL, a1i, 1);
                a0r = fmaf(sg, o0r, cg * a0r);
                a0i = fmaf(sg, o0i, cg * a0i);
                a1r = fmaf(sg, o1r, cg * a1r);
                a1i = fmaf(sg, o1i, cg * a1i);
            }
            // composed CNOT ring
            float t0r = __shfl_sync(FULL, a0r, s0cn);
            float t1r = __shfl_sync(FULL, a1r, s0cn);
            float u0r = __shfl_sync(FULL, a0r, s1cn);
            float u1r = __shfl_sync(FULL, a1r, s1cn);
            float t0i = __shfl_sync(FULL, a0i, s0cn);
            float t1i = __shfl_sync(FULL, a1i, s0cn);
            float u0i = __shfl_sync(FULL, a0i, s1cn);
            float u1i = __shfl_sync(FULL, a1i, s1cn);
            a0r = flipc ? t1r : t0r;  a0i = flipc ? t1i : t0i;
            a1r = flipc ? u0r : u1r;  a1i = flipc ? u0i : u1i;
        }

        // ---- fused measurement tree + FC update ----
        float pp = a0r * a0r + a0i * a0i;
        float pq = a1r * a1r + a1i * a1i;
        float ssum = pp + pq;
        float z0 = pp - pq;
        float xsh;
        xsh = __shfl_xor_sync(FULL, ssum, 16);
        float d4 = (l & 16) ? (xsh - ssum) : (ssum - xsh);
        ssum += xsh;
        z0 += __shfl_xor_sync(FULL, z0, 16);
        xsh = __shfl_xor_sync(FULL, ssum, 8);
        float d3 = (l & 8) ? (xsh - ssum) : (ssum - xsh);
        ssum += xsh;
        z0 += __shfl_xor_sync(FULL, z0, 8);
        d4 += __shfl_xor_sync(FULL, d4, 8);
        xsh = __shfl_xor_sync(FULL, ssum, 4);
        float d2 = (l & 4) ? (xsh - ssum) : (ssum - xsh);
        ssum += xsh;
        z0 += __shfl_xor_sync(FULL, z0, 4);
        d4 += __shfl_xor_sync(FULL, d4, 4);
        d3 += __shfl_xor_sync(FULL, d3, 4);
        xsh = __shfl_xor_sync(FULL, ssum, 2);
        float d1 = (l & 2) ? (xsh - ssum) : (ssum - xsh);
        ssum += xsh;
        z0 += __shfl_xor_sync(FULL, z0, 2);
        d4 += __shfl_xor_sync(FULL, d4, 2);
        d3 += __shfl_xor_sync(FULL, d3, 2);
        d2 += __shfl_xor_sync(FULL, d2, 2);
        xsh = __shfl_xor_sync(FULL, ssum, 1);
        float d0 = (l & 1) ? (xsh - ssum) : (ssum - xsh);
        z0 += __shfl_xor_sync(FULL, z0, 1);
        d4 += __shfl_xor_sync(FULL, d4, 1);
        d3 += __shfl_xor_sync(FULL, d3, 1);
        d2 += __shfl_xor_sync(FULL, d2, 1);
        d1 += __shfl_xor_sync(FULL, d1, 1);
        h = h + z0 * wfc0 + d4 * wfc1 + d3 * wfc2
              + d2 * wfc3 + d1 * wfc4 + d0 * wfc5 + bfcl;

        xt = xt_next;
    }

    if (TEND < TQ) {
        g_hs[bglob * HQ + l] = h;
        g_cs[bglob * HQ + l] = c;
    } else {
        float v = h * woutl;
        #pragma unroll
        for (int m = 16; m >= 1; m >>= 1) v += __shfl_xor_sync(FULL, v, m);
        if (l == 0) out[bglob] = sigmoid_acc(v + boutp[0]);
    }
}

// ---------------------------------------------------------------------------
extern "C" void kernel_launch(void* const* d_in, const int* in_sizes, int n_in,
                              void* d_out, int out_size) {
    const float* x   = (const float*)d_in[0];
    const float* w0  = (const float*)d_in[1];
    const float* b0  = (const float*)d_in[2];
    const float* w1  = (const float*)d_in[3];
    const float* b1  = (const float*)d_in[4];
    const float* w2  = (const float*)d_in[5];
    const float* b2  = (const float*)d_in[6];
    const float* Wih = (const float*)d_in[7];
    const float* Whh = (const float*)d_in[8];
    const float* bih = (const float*)d_in[9];
    const float* bhh = (const float*)d_in[10];
    const float* qw  = (const float*)d_in[11];
    const float* Wfc = (const float*)d_in[12];
    const float* bfc = (const float*)d_in[13];
    const float* Wout = (const float*)d_in[14];
    const float* bout = (const float*)d_in[15];
    float* out = (float*)d_out;

    prep_kernel<<<24, 256>>>(w0, w1, w2);
    conv_fused_kernel<<<BQ * 4, 256>>>(x, b0, b1, b2);
    recurrent_kernel<0, 128><<<BQ / 8, 256>>>(Wih, Whh, bih, bhh, qw, Wfc, bfc,
                                              Wout, bout, out);
    recurrent_kernel<128, 256><<<BQ / 8, 256>>>(Wih, Whh, bih, bhh, qw, Wfc, bfc,
                                                Wout, bout, out);
}

// round 7
// speedup vs baseline: 1.0763x; 1.0763x over previous
#include <cuda_runtime.h>
#include <math.h>

#define TQ 256
#define BQ 1024
#define DQ 64
#define HQ 32

// Scratch (no runtime allocation allowed)
__device__ float g_xt[TQ * BQ * HQ];                  // conv output, [t][b][o]
__device__ __align__(16) float g_w0t[192 * 32];       // vec4 layout, see prep
__device__ __align__(16) float g_w1t[96 * 32];
__device__ __align__(16) float g_w2t[96 * 32];
__device__ float g_hs[BQ * HQ];                       // persisted h between rec kernels
__device__ float g_cs[BQ * HQ];                       // persisted c

__device__ __forceinline__ float rcp_(float x) {
    float r; asm("rcp.approx.f32 %0, %1;" : "=f"(r) : "f"(x)); return r;
}
__device__ __forceinline__ float sigm_(float x) {
    return rcp_(1.0f + __expf(-x));
}
__device__ __forceinline__ float tanh_(float x) {
    return 1.0f - 2.0f * rcp_(1.0f + __expf(2.0f * x));
}
__device__ __forceinline__ float sigmoid_acc(float x) {
    return 1.0f / (1.0f + expf(-x));
}
__device__ __forceinline__ void fma2_(unsigned long long& acc,
                                      unsigned long long a,
                                      unsigned long long b) {
    asm("fma.rn.f32x2 %0, %1, %2, %3;" : "=l"(acc) : "l"(a), "l"(b), "l"(acc));
}
__device__ __forceinline__ float unpack_add_(unsigned long long acc) {
    float lo, hi;
    asm("mov.b64 {%0, %1}, %2;" : "=f"(lo), "=f"(hi) : "l"(acc));
    return lo + hi;
}
__device__ __forceinline__ unsigned long long pack2_(float lo, float hi) {
    unsigned long long r;
    asm("mov.b64 %0, {%1, %2};" : "=l"(r) : "f"(lo), "f"(hi));
    return r;
}

// ---------------------------------------------------------------------------
// Kernel 0: repack conv weights (unchanged).
// ---------------------------------------------------------------------------
__global__ void prep_kernel(const float* __restrict__ w0,
                            const float* __restrict__ w1,
                            const float* __restrict__ w2) {
    int i = threadIdx.x + blockIdx.x * 256;
    if (i < 6144) {
        int jj = i & 3, o = (i >> 2) & 31, kd4 = i >> 7;
        int k = kd4 >> 4, d4 = kd4 & 15;
        g_w0t[i] = w0[o * 192 + (4 * d4 + jj) * 3 + k];
    }
    if (i < 3072) {
        int jj = i & 3, o = (i >> 2) & 31, ki4 = i >> 7;
        int k = ki4 >> 3, i4 = ki4 & 7;
        g_w1t[i] = w1[o * 96 + (4 * i4 + jj) * 3 + k];
        g_w2t[i] = w2[o * 96 + (4 * i4 + jj) * 3 + k];
    }
}

// ---------------------------------------------------------------------------
// Generic conv row-group: NR output rows, ND4 = input width / 4.
// sv row pitch (in ulonglong2) == ND4. Weights wp laid out (k*ND4+d4)*32+o.
// ---------------------------------------------------------------------------
template <int NR, int ND4>
__device__ __forceinline__ void conv_group(
    const ulonglong2* __restrict__ wp, const ulonglong2* sv,
    int base, int o, float bz, float* av) {
    unsigned long long acc[NR];
    #pragma unroll
    for (int r = 0; r < NR; r++) acc[r] = 0ull;
    #pragma unroll
    for (int d4 = 0; d4 < ND4; d4++) {
        ulonglong2 wk0 = __ldg(&wp[d4 * 32 + o]);
        ulonglong2 wk1 = __ldg(&wp[(ND4 + d4) * 32 + o]);
        ulonglong2 wk2 = __ldg(&wp[(2 * ND4 + d4) * 32 + o]);
        ulonglong2 rr[NR + 2];
        #pragma unroll
        for (int r = 0; r < NR + 2; r++) rr[r] = sv[(base + r) * ND4 + d4];
        #pragma unroll
        for (int r = 0; r < NR; r++) {
            fma2_(acc[r], wk0.x, rr[r].x);     fma2_(acc[r], wk0.y, rr[r].y);
            fma2_(acc[r], wk1.x, rr[r + 1].x); fma2_(acc[r], wk1.y, rr[r + 1].y);
            fma2_(acc[r], wk2.x, rr[r + 2].x); fma2_(acc[r], wk2.y, rr[r + 2].y);
        }
    }
    #pragma unroll
    for (int r = 0; r < NR; r++) av[r] = unpack_add_(acc[r]) + bz;
}

// ---------------------------------------------------------------------------
// Kernel 1: fused 3-layer TCN, balanced 9/8 rows per warp on layers 0-1.
// s1 row r <-> time t0-2+r (68 rows, pad to 72, pad zeroed).
// s2 row r <-> time t0-1+r (68 rows computed; only rows 0..65 are read).
// ---------------------------------------------------------------------------
__global__ __launch_bounds__(256, 2) void conv_fused_kernel(
    const float* __restrict__ x,
    const float* __restrict__ b0, const float* __restrict__ b1,
    const float* __restrict__ b2) {
    __shared__ __align__(16) float xs[70 * 64];
    __shared__ __align__(16) float s1[72 * 32];
    __shared__ __align__(16) float s2[68 * 32];
    const ulonglong2* xs2 = (const ulonglong2*)xs;
    const ulonglong2* s1v = (const ulonglong2*)s1;
    const ulonglong2* s2v = (const ulonglong2*)s2;

    const int tid = threadIdx.x;
    const int b = blockIdx.x >> 2;
    const int t0 = (blockIdx.x & 3) * 64;

    for (int i = tid; i < 70 * 64; i += 256) {
        int r = i >> 6, d = i & 63, t = t0 - 3 + r;
        xs[i] = (t >= 0 && t < TQ) ? x[b * TQ * DQ + t * DQ + d] : 0.0f;
    }
    if (tid < 128) s1[68 * 32 + tid] = 0.0f;     // zero pad rows 68..71
    __syncthreads();

    const int w = tid >> 5, o = tid & 31;
    const ulonglong2* wp0 = (const ulonglong2*)g_w0t;
    const ulonglong2* wp1 = (const ulonglong2*)g_w1t;
    const ulonglong2* wp2 = (const ulonglong2*)g_w2t;

    // row assignment for layers 0-1: warps 0-3 get 9 rows, warps 4-7 get 8
    const int rbase = (w < 4) ? 9 * w : 36 + 8 * (w - 4);
    const bool nine = (w < 4);

    // ---- layer 0: 68 rows (times t0-2+row) ----
    {
        float bz = __ldg(&b0[o]);
        float av[9];
        conv_group<4, 16>(wp0, xs2, rbase, o, bz, av);
        if (nine) conv_group<5, 16>(wp0, xs2, rbase + 4, o, bz, av + 4);
        else      conv_group<4, 16>(wp0, xs2, rbase + 4, o, bz, av + 4);
        const int n = nine ? 9 : 8;
        #pragma unroll
        for (int r = 0; r < 9; r++) {
            if (r < n) {
                int row = rbase + r, tt = t0 - 2 + row;
                float v = fmaxf(av[r], 0.0f);
                if (tt < 0 || tt >= TQ) v = 0.0f;
                s1[row * 32 + o] = v;
            }
        }
    }
    __syncthreads();

    // ---- layer 1: 68 rows computed (rows 66-67 are never read) ----
    {
        float bz = __ldg(&b1[o]);
        float av[9];
        conv_group<4, 8>(wp1, s1v, rbase, o, bz, av);
        if (nine) conv_group<5, 8>(wp1, s1v, rbase + 4, o, bz, av + 4);
        else      conv_group<4, 8>(wp1, s1v, rbase + 4, o, bz, av + 4);
        const int n = nine ? 9 : 8;
        #pragma unroll
        for (int r = 0; r < 9; r++) {
            if (r < n) {
                int row = rbase + r, tt = t0 - 1 + row;
                float v = fmaxf(av[r], 0.0f);
                if (tt < 0 || tt >= TQ) v = 0.0f;
                s2[row * 32 + o] = v;
            }
        }
    }
    __syncthreads();

    // ---- layer 2: 64 rows, 8 per warp (balanced) -> global ----
    {
        float bz = __ldg(&b2[o]);
        float av[8];
        conv_group<4, 8>(wp2, s2v, 8 * w, o, bz, av);
        conv_group<4, 8>(wp2, s2v, 8 * w + 4, o, bz, av + 4);
        #pragma unroll
        for (int r = 0; r < 8; r++) {
            const int t = t0 + 8 * w + r;
            g_xt[t * (BQ * HQ) + b * HQ + o] = fmaxf(av[r], 0.0f);
        }
    }
}

// ---------------------------------------------------------------------------
// Kernel 2: recurrent scan over [TSTART, TEND).
// Matvec: k-pair packed weights, batch-major activations (R5).
// Quantum: sequential RY gates (R4 path) + Walsh-Hadamard measurement (15 shfl).
// ---------------------------------------------------------------------------
template <int TSTART, int TEND>
__global__ __launch_bounds__(256, 1) void recurrent_kernel(
    const float* __restrict__ Wih, const float* __restrict__ Whh,
    const float* __restrict__ bih, const float* __restrict__ bhh,
    const float* __restrict__ qweights,
    const float* __restrict__ Wfc, const float* __restrict__ bfc,
    const float* __restrict__ Wout, const float* __restrict__ boutp,
    float* __restrict__ out) {
    __shared__ __align__(16) float xhf[2][256];     // [half][b*64 + idx]
    __shared__ float gsm[2][128 * 5];               // [half][j*5 + bb]
    __shared__ float qc[18], qs[18];

    const unsigned FULL = 0xffffffffu;
    const int tid = threadIdx.x;
    const int l = tid & 31;
    const int wrp = tid >> 5;
    const int half = tid >> 7;
    const int wb = wrp & 3;
    const int bglob = blockIdx.x * 8 + wrp;
    const int j = tid & 127;
    const int barid = half + 1;

    // ---- pack weight column j as adjacent-k pairs (32 u64 = 64 regs) ----
    unsigned long long wpk[32];
    #pragma unroll
    for (int p = 0; p < 16; p++)
        wpk[p] = pack2_(Wih[j * 32 + 2 * p], Wih[j * 32 + 2 * p + 1]);
    #pragma unroll
    for (int p = 0; p < 16; p++)
        wpk[16 + p] = pack2_(Whh[j * 32 + 2 * p], Whh[j * 32 + 2 * p + 1]);
    const float biasj = bih[j] + bhh[j];

    if (tid < 18) {
        float a = 0.5f * qweights[tid];
        qc[tid] = cosf(a);
        qs[tid] = sinf(a);
    }

    const float wfc0 = Wfc[l * 6 + 0], wfc1 = Wfc[l * 6 + 1], wfc2 = Wfc[l * 6 + 2];
    const float wfc3 = Wfc[l * 6 + 3], wfc4 = Wfc[l * 6 + 4], wfc5 = Wfc[l * 6 + 5];
    const float bfcl = bfc[l];
    const float woutl = Wout[l];
    // composed CNOT-ring source lanes
    const int s0cn = ((l ^ (l >> 1)) & 0x0F) | ((((l >> 4) ^ l) & 1) << 4);
    const int s1cn = s0cn ^ 16;
    const bool flipc = (l & 1) != 0;

    float h, c;
    if (TSTART == 0) {
        h = 0.0f; c = 0.0f;
    } else {
        h = g_hs[bglob * HQ + l];
        c = g_cs[bglob * HQ + l];
    }
    __syncthreads();   // qc/qs visible

    float xt = g_xt[TSTART * (BQ * HQ) + bglob * HQ + l];

    for (int t = TSTART; t < TEND; t++) {
        // ---- stage activations batch-major: [b*64 + k] ----
        xhf[half][wb * 64 + l] = xt;
        xhf[half][wb * 64 + 32 + l] = h;
        asm volatile("bar.sync %0, 128;" :: "r"(barid) : "memory");

        float xt_next = 0.0f;
        if (t + 1 < TQ) xt_next = g_xt[(t + 1) * (BQ * HQ) + bglob * HQ + l];

        // ---- matvec: acc lanes hold even/odd-k partial sums ----
        {
            unsigned long long a0 = 0ull, a1 = 0ull, a2 = 0ull, a3 = 0ull;
            const ulonglong2* xv = (const ulonglong2*)&xhf[half][0];
            #pragma unroll
            for (int kg = 0; kg < 16; kg++) {
                ulonglong2 x0 = xv[kg];
                ulonglong2 x1 = xv[16 + kg];
                ulonglong2 x2 = xv[32 + kg];
                ulonglong2 x3 = xv[48 + kg];
                fma2_(a0, wpk[2 * kg], x0.x); fma2_(a0, wpk[2 * kg + 1], x0.y);
                fma2_(a1, wpk[2 * kg], x1.x); fma2_(a1, wpk[2 * kg + 1], x1.y);
                fma2_(a2, wpk[2 * kg], x2.x); fma2_(a2, wpk[2 * kg + 1], x2.y);
                fma2_(a3, wpk[2 * kg], x3.x); fma2_(a3, wpk[2 * kg + 1], x3.y);
            }
            gsm[half][j * 5 + 0] = unpack_add_(a0) + biasj;
            gsm[half][j * 5 + 1] = unpack_add_(a1) + biasj;
            gsm[half][j * 5 + 2] = unpack_add_(a2) + biasj;
            gsm[half][j * 5 + 3] = unpack_add_(a3) + biasj;
        }
        asm volatile("bar.sync %0, 128;" :: "r"(barid) : "memory");

        // ---- LSTM cell + chaotic maps ----
        float gi = gsm[half][l * 5 + wb];
        float gf = gsm[half][(l + 32) * 5 + wb];
        float gg = gsm[half][(l + 64) * 5 + wb];
        float go = gsm[half][(l + 96) * 5 + wb];
        c = sigm_(gf) * c + sigm_(gi) * tanh_(gg);
        h = sigm_(go) * tanh_(c);
        h = 3.99f * h * (1.0f - h);
        float x0h = __shfl_sync(FULL, h, 0);
        float y0h = __shfl_sync(FULL, h, 1);
        if (l == 0) h = 1.0f - 1.4f * (x0h * x0h) + y0h;
        if (l == 1) h = 0.3f * x0h;

        // ---- 6-qubit circuit ----
        float ang = (l < 6) ? 0.5f * h : 0.0f;
        float ssin, scos;
        __sincosf(ang, &ssin, &scos);
        float cs[6], sn[6];
        #pragma unroll
        for (int q = 0; q < 6; q++) {
            cs[q] = __shfl_sync(FULL, scos, q);
            sn[q] = __shfl_sync(FULL, ssin, q);
        }
        float p0r[6], p0i[6], p1r[6], p1i[6];
        #pragma unroll
        for (int i = 0; i < 6; i++) {
            const int i1 = (i + 1) % 6, i2 = (i + 2) % 6;
            float cx = cs[i], sx = sn[i];
            float cy = cs[i1], sy = sn[i1];
            float cz = cs[i2], sz = sn[i2];
            float ur = cy * cx, ui = sy * sx;
            float vr = sy * cx, vi = -(cy * sx);
            p0r[i] = ur * cz + ui * sz;
            p0i[i] = ui * cz - ur * sz;
            p1r[i] = vr * cz - vi * sz;
            p1i[i] = vi * cz + vr * sz;
        }
        float cr = 1.0f, cii = 0.0f;
        #pragma unroll
        for (int q = 1; q < 6; q++) {
            int bit = (l >> (5 - q)) & 1;
            float fr = bit ? p1r[q] : p0r[q];
            float fi = bit ? p1i[q] : p0i[q];
            float nr = cr * fr - cii * fi;
            float ni = cr * fi + cii * fr;
            cr = nr; cii = ni;
        }
        float a0r = cr * p0r[0] - cii * p0i[0];
        float a0i = cr * p0i[0] + cii * p0r[0];
        float a1r = cr * p1r[0] - cii * p1i[0];
        float a1i = cr * p1i[0] + cii * p1r[0];

        #pragma unroll
        for (int lay = 0; lay < 3; lay++) {
            {   // RY q=0 (register pair, no shfl)
                float cg = qc[lay * 6 + 0], sg = qs[lay * 6 + 0];
                float n0r = cg * a0r - sg * a1r, n0i = cg * a0i - sg * a1i;
                float n1r = sg * a0r + cg * a1r, n1i = sg * a0i + cg * a1i;
                a0r = n0r; a0i = n0i; a1r = n1r; a1i = n1i;
            }
            #pragma unroll
            for (int q = 1; q < 6; q++) {   // RY q=1..5 via shfl_xor
                const int m = 1 << (5 - q);
                float cg = qc[lay * 6 + q], sg = qs[lay * 6 + q];
                float sgn = (l & m) ? sg : -sg;
                float o0r = __shfl_xor_sync(FULL, a0r, m);
                float o0i = __shfl_xor_sync(FULL, a0i, m);
                float o1r = __shfl_xor_sync(FULL, a1r, m);
                float o1i = __shfl_xor_sync(FULL, a1i, m);
                a0r = fmaf(sgn, o0r, cg * a0r);
                a0i = fmaf(sgn, o0i, cg * a0i);
                a1r = fmaf(sgn, o1r, cg * a1r);
                a1i = fmaf(sgn, o1i, cg * a1i);
            }
            // composed CNOT ring
            float t0r = __shfl_sync(FULL, a0r, s0cn);
            float t1r = __shfl_sync(FULL, a1r, s0cn);
            float u0r = __shfl_sync(FULL, a0r, s1cn);
            float u1r = __shfl_sync(FULL, a1r, s1cn);
            float t0i = __shfl_sync(FULL, a0i, s0cn);
            float t1i = __shfl_sync(FULL, a1i, s0cn);
            float u0i = __shfl_sync(FULL, a0i, s1cn);
            float u1i = __shfl_sync(FULL, a1i, s1cn);
            a0r = flipc ? t1r : t0r;  a0i = flipc ? t1i : t0i;
            a1r = flipc ? u0r : u1r;  a1i = flipc ? u0i : u1i;
        }

        // ---- Walsh-Hadamard measurement (15 shfls) + FC update ----
        float pp = a0r * a0r + a0i * a0i;
        float pq = a1r * a1r + a1i * a1i;
        float s = pp + pq;
        float d = pp - pq;
        // WHT butterfly: lane k ends with S_hat[k] = sum_m (-1)^{popc(k&m)} s_m
        #pragma unroll
        for (int b = 4; b >= 0; b--) {
            const int m = 1 << b;
            float o = __shfl_xor_sync(FULL, s, m);
            s = (l & m) ? (o - s) : (s + o);
        }
        // plain all-reduce for e0
        #pragma unroll
        for (int m = 16; m >= 1; m >>= 1) d += __shfl_xor_sync(FULL, d, m);
        float e1 = __shfl_sync(FULL, s, 16);
        float e2 = __shfl_sync(FULL, s, 8);
        float e3 = __shfl_sync(FULL, s, 4);
        float e4 = __shfl_sync(FULL, s, 2);
        float e5 = __shfl_sync(FULL, s, 1);
        h = h + d * wfc0 + e1 * wfc1 + e2 * wfc2
              + e3 * wfc3 + e4 * wfc4 + e5 * wfc5 + bfcl;

        xt = xt_next;
    }

    if (TEND < TQ) {
        g_hs[bglob * HQ + l] = h;
        g_cs[bglob * HQ + l] = c;
    } else {
        float v = h * woutl;
        #pragma unroll
        for (int m = 16; m >= 1; m >>= 1) v += __shfl_xor_sync(FULL, v, m);
        if (l == 0) out[bglob] = sigmoid_acc(v + boutp[0]);
    }
}

// ---------------------------------------------------------------------------
extern "C" void kernel_launch(void* const* d_in, const int* in_sizes, int n_in,
                              void* d_out, int out_size) {
    const float* x   = (const float*)d_in[0];
    const float* w0  = (const float*)d_in[1];
    const float* b0  = (const float*)d_in[2];
    const float* w1  = (const float*)d_in[3];
    const float* b1  = (const float*)d_in[4];
    const float* w2  = (const float*)d_in[5];
    const float* b2  = (const float*)d_in[6];
    const float* Wih = (const float*)d_in[7];
    const float* Whh = (const float*)d_in[8];
    const float* bih = (const float*)d_in[9];
    const float* bhh = (const float*)d_in[10];
    const float* qw  = (const float*)d_in[11];
    const float* Wfc = (const float*)d_in[12];
    const float* bfc = (const float*)d_in[13];
    const float* Wout = (const float*)d_in[14];
    const float* bout = (const float*)d_in[15];
    float* out = (float*)d_out;

    prep_kernel<<<24, 256>>>(w0, w1, w2);
    conv_fused_kernel<<<BQ * 4, 256>>>(x, b0, b1, b2);
    recurrent_kernel<0, 128><<<BQ / 8, 256>>>(Wih, Whh, bih, bhh, qw, Wfc, bfc,
                                              Wout, bout, out);
    recurrent_kernel<128, 256><<<BQ / 8, 256>>>(Wih, Whh, bih, bhh, qw, Wfc, bfc,
                                                Wout, bout, out);
}

// round 8
// speedup vs baseline: 1.2699x; 1.1799x over previous
#include <cuda_runtime.h>
#include <math.h>

#define TQ 256
#define BQ 1024
#define DQ 64
#define HQ 32

// Scratch (no runtime allocation allowed)
__device__ float g_xt[TQ * BQ * HQ];                  // conv output, [t][b][o]
__device__ __align__(16) float g_w0t[192 * 32];       // vec4 layout, see prep
__device__ __align__(16) float g_w1t[96 * 32];
__device__ __align__(16) float g_w2t[96 * 32];
__device__ float g_hs[BQ * HQ];                       // persisted h between rec kernels
__device__ float g_cs[BQ * HQ];                       // persisted c

__device__ __forceinline__ float rcp_(float x) {
    float r; asm("rcp.approx.f32 %0, %1;" : "=f"(r) : "f"(x)); return r;
}
__device__ __forceinline__ float sigm_(float x) {
    return rcp_(1.0f + __expf(-x));
}
__device__ __forceinline__ float tanh_(float x) {
    return 1.0f - 2.0f * rcp_(1.0f + __expf(2.0f * x));
}
__device__ __forceinline__ float sigmoid_acc(float x) {
    return 1.0f / (1.0f + expf(-x));
}
__device__ __forceinline__ void fma2_(unsigned long long& acc,
                                      unsigned long long a,
                                      unsigned long long b) {
    asm("fma.rn.f32x2 %0, %1, %2, %3;" : "=l"(acc) : "l"(a), "l"(b), "l"(acc));
}
__device__ __forceinline__ float unpack_add_(unsigned long long acc) {
    float lo, hi;
    asm("mov.b64 {%0, %1}, %2;" : "=f"(lo), "=f"(hi) : "l"(acc));
    return lo + hi;
}
__device__ __forceinline__ unsigned long long pack2_(float lo, float hi) {
    unsigned long long r;
    asm("mov.b64 %0, {%1, %2};" : "=l"(r) : "f"(lo), "f"(hi));
    return r;
}

// ---------------------------------------------------------------------------
// Kernel 0: repack conv weights (unchanged).
// ---------------------------------------------------------------------------
__global__ void prep_kernel(const float* __restrict__ w0,
                            const float* __restrict__ w1,
                            const float* __restrict__ w2) {
    int i = threadIdx.x + blockIdx.x * 256;
    if (i < 6144) {
        int jj = i & 3, o = (i >> 2) & 31, kd4 = i >> 7;
        int k = kd4 >> 4, d4 = kd4 & 15;
        g_w0t[i] = w0[o * 192 + (4 * d4 + jj) * 3 + k];
    }
    if (i < 3072) {
        int jj = i & 3, o = (i >> 2) & 31, ki4 = i >> 7;
        int k = ki4 >> 3, i4 = ki4 & 7;
        g_w1t[i] = w1[o * 96 + (4 * i4 + jj) * 3 + k];
        g_w2t[i] = w2[o * 96 + (4 * i4 + jj) * 3 + k];
    }
}

// ---------------------------------------------------------------------------
// Generic conv row-group (unchanged from R6).
// ---------------------------------------------------------------------------
template <int NR, int ND4>
__device__ __forceinline__ void conv_group(
    const ulonglong2* __restrict__ wp, const ulonglong2* sv,
    int base, int o, float bz, float* av) {
    unsigned long long acc[NR];
    #pragma unroll
    for (int r = 0; r < NR; r++) acc[r] = 0ull;
    #pragma unroll
    for (int d4 = 0; d4 < ND4; d4++) {
        ulonglong2 wk0 = __ldg(&wp[d4 * 32 + o]);
        ulonglong2 wk1 = __ldg(&wp[(ND4 + d4) * 32 + o]);
        ulonglong2 wk2 = __ldg(&wp[(2 * ND4 + d4) * 32 + o]);
        ulonglong2 rr[NR + 2];
        #pragma unroll
        for (int r = 0; r < NR + 2; r++) rr[r] = sv[(base + r) * ND4 + d4];
        #pragma unroll
        for (int r = 0; r < NR; r++) {
            fma2_(acc[r], wk0.x, rr[r].x);     fma2_(acc[r], wk0.y, rr[r].y);
            fma2_(acc[r], wk1.x, rr[r + 1].x); fma2_(acc[r], wk1.y, rr[r + 1].y);
            fma2_(acc[r], wk2.x, rr[r + 2].x); fma2_(acc[r], wk2.y, rr[r + 2].y);
        }
    }
    #pragma unroll
    for (int r = 0; r < NR; r++) av[r] = unpack_add_(acc[r]) + bz;
}

// ---------------------------------------------------------------------------
// Kernel 1: fused 3-layer TCN, balanced 9/8 rows per warp (R6) + float4 loads.
// ---------------------------------------------------------------------------
__global__ __launch_bounds__(256, 2) void conv_fused_kernel(
    const float* __restrict__ x,
    const float* __restrict__ b0, const float* __restrict__ b1,
    const float* __restrict__ b2) {
    __shared__ __align__(16) float xs[70 * 64];
    __shared__ __align__(16) float s1[72 * 32];
    __shared__ __align__(16) float s2[68 * 32];
    const ulonglong2* xs2 = (const ulonglong2*)xs;
    const ulonglong2* s1v = (const ulonglong2*)s1;
    const ulonglong2* s2v = (const ulonglong2*)s2;

    const int tid = threadIdx.x;
    const int b = blockIdx.x >> 2;
    const int t0 = (blockIdx.x & 3) * 64;

    // vectorized xs fill (x rows are 64 contiguous, 16B-aligned floats)
    {
        float4* xs4f = (float4*)xs;
        const float4 zero4 = make_float4(0.f, 0.f, 0.f, 0.f);
        for (int i = tid; i < 70 * 16; i += 256) {
            int r = i >> 4, d4 = i & 15, t = t0 - 3 + r;
            xs4f[i] = (t >= 0 && t < TQ)
                ? __ldg((const float4*)(x + b * TQ * DQ + t * DQ + d4 * 4))
                : zero4;
        }
    }
    if (tid < 128) s1[68 * 32 + tid] = 0.0f;     // zero pad rows 68..71
    __syncthreads();

    const int w = tid >> 5, o = tid & 31;
    const ulonglong2* wp0 = (const ulonglong2*)g_w0t;
    const ulonglong2* wp1 = (const ulonglong2*)g_w1t;
    const ulonglong2* wp2 = (const ulonglong2*)g_w2t;

    const int rbase = (w < 4) ? 9 * w : 36 + 8 * (w - 4);
    const bool nine = (w < 4);

    // ---- layer 0 ----
    {
        float bz = __ldg(&b0[o]);
        float av[9];
        conv_group<4, 16>(wp0, xs2, rbase, o, bz, av);
        if (nine) conv_group<5, 16>(wp0, xs2, rbase + 4, o, bz, av + 4);
        else      conv_group<4, 16>(wp0, xs2, rbase + 4, o, bz, av + 4);
        const int n = nine ? 9 : 8;
        #pragma unroll
        for (int r = 0; r < 9; r++) {
            if (r < n) {
                int row = rbase + r, tt = t0 - 2 + row;
                float v = fmaxf(av[r], 0.0f);
                if (tt < 0 || tt >= TQ) v = 0.0f;
                s1[row * 32 + o] = v;
            }
        }
    }
    __syncthreads();

    // ---- layer 1 ----
    {
        float bz = __ldg(&b1[o]);
        float av[9];
        conv_group<4, 8>(wp1, s1v, rbase, o, bz, av);
        if (nine) conv_group<5, 8>(wp1, s1v, rbase + 4, o, bz, av + 4);
        else      conv_group<4, 8>(wp1, s1v, rbase + 4, o, bz, av + 4);
        const int n = nine ? 9 : 8;
        #pragma unroll
        for (int r = 0; r < 9; r++) {
            if (r < n) {
                int row = rbase + r, tt = t0 - 1 + row;
                float v = fmaxf(av[r], 0.0f);
                if (tt < 0 || tt >= TQ) v = 0.0f;
                s2[row * 32 + o] = v;
            }
        }
    }
    __syncthreads();

    // ---- layer 2 ----
    {
        float bz = __ldg(&b2[o]);
        float av[8];
        conv_group<4, 8>(wp2, s2v, 8 * w, o, bz, av);
        conv_group<4, 8>(wp2, s2v, 8 * w + 4, o, bz, av + 4);
        #pragma unroll
        for (int r = 0; r < 8; r++) {
            const int t = t0 + 8 * w + r;
            g_xt[t * (BQ * HQ) + b * HQ + o] = fmaxf(av[r], 0.0f);
        }
    }
}

// ---------------------------------------------------------------------------
// Conjugated RY gate: partner mask = (MREG? reg flip : none) + lane mask LAM.
// a_new[m] = c*a[m] + sgn(m)*s*a[m^M], sgn precomputed per lane.
// ---------------------------------------------------------------------------
#define QGATE(MREG, LAM, G) do { \
    float b0r_ = (MREG) ? a1r : a0r; \
    float b0i_ = (MREG) ? a1i : a0i; \
    float b1r_ = (MREG) ? a0r : a1r; \
    float b1i_ = (MREG) ? a0i : a1i; \
    float o0r_ = __shfl_xor_sync(FULL, b0r_, (LAM)); \
    float o0i_ = __shfl_xor_sync(FULL, b0i_, (LAM)); \
    float o1r_ = __shfl_xor_sync(FULL, b1r_, (LAM)); \
    float o1i_ = __shfl_xor_sync(FULL, b1i_, (LAM)); \
    a0r = fmaf(gs0[G], o0r_, gc[G] * a0r); \
    a0i = fmaf(gs0[G], o0i_, gc[G] * a0i); \
    a1r = fmaf(gs1[G], o1r_, gc[G] * a1r); \
    a1i = fmaf(gs1[G], o1i_, gc[G] * a1i); \
} while (0)

// ---------------------------------------------------------------------------
// Kernel 2: recurrent scan over [TSTART, TEND).
// Quantum: layer-1 RY folded into product kets (0 shfl); CNOT rings commuted
// to the end via GF(2) conjugation (masks below) and absorbed into the
// Walsh-Hadamard measurement indices. 78 shfls/step (was 113).
// ---------------------------------------------------------------------------
template <int TSTART, int TEND>
__global__ __launch_bounds__(256, 1) void recurrent_kernel(
    const float* __restrict__ Wih, const float* __restrict__ Whh,
    const float* __restrict__ bih, const float* __restrict__ bhh,
    const float* __restrict__ qweights,
    const float* __restrict__ Wfc, const float* __restrict__ bfc,
    const float* __restrict__ Wout, const float* __restrict__ boutp,
    float* __restrict__ out) {
    __shared__ __align__(16) float xhf[2][256];     // [half][b*64 + idx]
    __shared__ float gsm[2][128 * 5];               // [half][j*5 + bb]
    __shared__ float qc[18], qs[18];

    const unsigned FULL = 0xffffffffu;
    const int tid = threadIdx.x;
    const int l = tid & 31;
    const int wrp = tid >> 5;
    const int half = tid >> 7;
    const int wb = wrp & 3;
    const int bglob = blockIdx.x * 8 + wrp;
    const int j = tid & 127;
    const int barid = half + 1;

    // ---- pack weight column j as adjacent-k pairs ----
    unsigned long long wpk[32];
    #pragma unroll
    for (int p = 0; p < 16; p++)
        wpk[p] = pack2_(Wih[j * 32 + 2 * p], Wih[j * 32 + 2 * p + 1]);
    #pragma unroll
    for (int p = 0; p < 16; p++)
        wpk[16 + p] = pack2_(Whh[j * 32 + 2 * p], Whh[j * 32 + 2 * p + 1]);
    const float biasj = bih[j] + bhh[j];

    if (tid < 18) {
        float a = 0.5f * qweights[tid];
        qc[tid] = cosf(a);
        qs[tid] = sinf(a);
    }

    const float wfc0 = Wfc[l * 6 + 0], wfc1 = Wfc[l * 6 + 1], wfc2 = Wfc[l * 6 + 2];
    const float wfc3 = Wfc[l * 6 + 3], wfc4 = Wfc[l * 6 + 4], wfc5 = Wfc[l * 6 + 5];
    const float bfcl = bfc[l];
    const float woutl = Wout[l];
    __syncthreads();   // qc/qs visible

    // ---- layer-1 RY coefficients (folded into kets) ----
    float c1q[6], s1q[6];
    #pragma unroll
    for (int q = 0; q < 6; q++) { c1q[q] = qc[q]; s1q[q] = qs[q]; }

    // ---- conjugated-gate coefficients: sign = parity(l & PHI) (^GREG on a1) ----
    // gates 0-5: layer2 (masks L^-1 e_q, signs row_q(L));
    // gates 6-11: layer3 (masks L^-2 e_q, signs row_q(L^2)).
    const int PHI[12]  = {31, 16, 24, 28, 30, 31, 21, 15, 23, 11, 21, 10};
    const int GREG[12] = { 0,  1,  1,  1,  1,  1,  1,  1,  0,  1,  0,  1};
    float gc[12], gs0[12], gs1[12];
    #pragma unroll
    for (int g = 0; g < 12; g++) {
        const int idx = 6 + g;        // qc/qs index: layers 2,3 = entries 6..17
        float cg = qc[idx], sg = qs[idx];
        int f0 = __popc(l & PHI[g]) & 1;
        gc[g] = cg;
        gs0[g] = f0 ? sg : -sg;
        gs1[g] = (f0 ^ GREG[g]) ? sg : -sg;
    }

    float h, c;
    if (TSTART == 0) {
        h = 0.0f; c = 0.0f;
    } else {
        h = g_hs[bglob * HQ + l];
        c = g_cs[bglob * HQ + l];
    }

    float xt = g_xt[TSTART * (BQ * HQ) + bglob * HQ + l];

    for (int t = TSTART; t < TEND; t++) {
        // ---- stage activations batch-major: [b*64 + k] ----
        xhf[half][wb * 64 + l] = xt;
        xhf[half][wb * 64 + 32 + l] = h;
        asm volatile("bar.sync %0, 128;" :: "r"(barid) : "memory");

        float xt_next = 0.0f;
        if (t + 1 < TQ) xt_next = g_xt[(t + 1) * (BQ * HQ) + bglob * HQ + l];

        // ---- matvec ----
        {
            unsigned long long a0 = 0ull, a1 = 0ull, a2 = 0ull, a3 = 0ull;
            const ulonglong2* xv = (const ulonglong2*)&xhf[half][0];
            #pragma unroll
            for (int kg = 0; kg < 16; kg++) {
                ulonglong2 x0 = xv[kg];
                ulonglong2 x1 = xv[16 + kg];
                ulonglong2 x2 = xv[32 + kg];
                ulonglong2 x3 = xv[48 + kg];
                fma2_(a0, wpk[2 * kg], x0.x); fma2_(a0, wpk[2 * kg + 1], x0.y);
                fma2_(a1, wpk[2 * kg], x1.x); fma2_(a1, wpk[2 * kg + 1], x1.y);
                fma2_(a2, wpk[2 * kg], x2.x); fma2_(a2, wpk[2 * kg + 1], x2.y);
                fma2_(a3, wpk[2 * kg], x3.x); fma2_(a3, wpk[2 * kg + 1], x3.y);
            }
            gsm[half][j * 5 + 0] = unpack_add_(a0) + biasj;
            gsm[half][j * 5 + 1] = unpack_add_(a1) + biasj;
            gsm[half][j * 5 + 2] = unpack_add_(a2) + biasj;
            gsm[half][j * 5 + 3] = unpack_add_(a3) + biasj;
        }
        asm volatile("bar.sync %0, 128;" :: "r"(barid) : "memory");

        // ---- LSTM cell + chaotic maps ----
        float gi = gsm[half][l * 5 + wb];
        float gf = gsm[half][(l + 32) * 5 + wb];
        float gg = gsm[half][(l + 64) * 5 + wb];
        float go = gsm[half][(l + 96) * 5 + wb];
        c = sigm_(gf) * c + sigm_(gi) * tanh_(gg);
        h = sigm_(go) * tanh_(c);
        h = 3.99f * h * (1.0f - h);
        float x0h = __shfl_sync(FULL, h, 0);
        float y0h = __shfl_sync(FULL, h, 1);
        if (l == 0) h = 1.0f - 1.4f * (x0h * x0h) + y0h;
        if (l == 1) h = 0.3f * x0h;

        // ---- 6-qubit circuit ----
        float ang = (l < 6) ? 0.5f * h : 0.0f;
        float ssin, scos;
        __sincosf(ang, &ssin, &scos);
        float cs[6], sn[6];
        #pragma unroll
        for (int q = 0; q < 6; q++) {
            cs[q] = __shfl_sync(FULL, scos, q);
            sn[q] = __shfl_sync(FULL, ssin, q);
        }
        // kets psi_i = RY(layer1) * RZ * RY * RX |0>   (layer-1 RY folded in)
        float p0r[6], p0i[6], p1r[6], p1i[6];
        #pragma unroll
        for (int i = 0; i < 6; i++) {
            const int i1 = (i + 1) % 6, i2 = (i + 2) % 6;
            float cx = cs[i], sx = sn[i];
            float cy = cs[i1], sy = sn[i1];
            float cz = cs[i2], sz = sn[i2];
            float ur = cy * cx, ui = sy * sx;
            float vr = sy * cx, vi = -(cy * sx);
            float q0r = ur * cz + ui * sz;
            float q0i = ui * cz - ur * sz;
            float q1r = vr * cz - vi * sz;
            float q1i = vi * cz + vr * sz;
            float cv = c1q[i], sv = s1q[i];
            p0r[i] = cv * q0r - sv * q1r;
            p0i[i] = cv * q0i - sv * q1i;
            p1r[i] = sv * q0r + cv * q1r;
            p1i[i] = sv * q0i + cv * q1i;
        }
        // product state: factor over qubits 1..5 (lane bits), split qubit 0
        float cr = 1.0f, cii = 0.0f;
        #pragma unroll
        for (int q = 1; q < 6; q++) {
            int bit = (l >> (5 - q)) & 1;
            float fr = bit ? p1r[q] : p0r[q];
            float fi = bit ? p1i[q] : p0i[q];
            float nr = cr * fr - cii * fi;
            float ni = cr * fi + cii * fr;
            cr = nr; cii = ni;
        }
        float a0r = cr * p0r[0] - cii * p0i[0];
        float a0i = cr * p0i[0] + cii * p0r[0];
        float a1r = cr * p1r[0] - cii * p1i[0];
        float a1i = cr * p1i[0] + cii * p1r[0];

        // ---- conjugated variational gates (12 x 4 shfls, no CNOTs) ----
        QGATE(1, 16, 0);  QGATE(0, 24, 1);  QGATE(0, 12, 2);
        QGATE(0, 6, 3);   QGATE(0, 3, 4);   QGATE(1, 17, 5);
        QGATE(1, 8, 6);   QGATE(0, 20, 7);  QGATE(0, 10, 8);
        QGATE(0, 5, 9);   QGATE(1, 18, 10); QGATE(0, 25, 11);

        // ---- measurement: dual WHT; CNOT perms absorbed into Walsh indices ----
        float pp = a0r * a0r + a0i * a0i;
        float pq = a1r * a1r + a1i * a1i;
        float u = pp + pq;          // for evs with reg-bit 0 in Walsh index
        float wv = pp - pq;         // for evs with reg-bit 1
        #pragma unroll
        for (int bmask = 16; bmask >= 1; bmask >>= 1) {
            float ou = __shfl_xor_sync(FULL, u, bmask);
            u = (l & bmask) ? (ou - u) : (u + ou);
            float ow = __shfl_xor_sync(FULL, wv, bmask);
            wv = (l & bmask) ? (ow - wv) : (wv + ow);
        }
        // E[Z_q] at Walsh index row_q(L^3): q0->w[12], q1->u[26], q2->u[13],
        // q3->w[6], q4->w[19], q5->u[25]
        float e0 = __shfl_sync(FULL, wv, 12);
        float e1 = __shfl_sync(FULL, u, 26);
        float e2 = __shfl_sync(FULL, u, 13);
        float e3 = __shfl_sync(FULL, wv, 6);
        float e4 = __shfl_sync(FULL, wv, 19);
        float e5 = __shfl_sync(FULL, u, 25);
        h = h + e0 * wfc0 + e1 * wfc1 + e2 * wfc2
              + e3 * wfc3 + e4 * wfc4 + e5 * wfc5 + bfcl;

        xt = xt_next;
    }

    if (TEND < TQ) {
        g_hs[bglob * HQ + l] = h;
        g_cs[bglob * HQ + l] = c;
    } else {
        float v = h * woutl;
        #pragma unroll
        for (int m = 16; m >= 1; m >>= 1) v += __shfl_xor_sync(FULL, v, m);
        if (l == 0) out[bglob] = sigmoid_acc(v + boutp[0]);
    }
}

// ---------------------------------------------------------------------------
extern "C" void kernel_launch(void* const* d_in, const int* in_sizes, int n_in,
                              void* d_out, int out_size) {
    const float* x   = (const float*)d_in[0];
    const float* w0  = (const float*)d_in[1];
    const float* b0  = (const float*)d_in[2];
    const float* w1  = (const float*)d_in[3];
    const float* b1  = (const float*)d_in[4];
    const float* w2  = (const float*)d_in[5];
    const float* b2  = (const float*)d_in[6];
    const float* Wih = (const float*)d_in[7];
    const float* Whh = (const float*)d_in[8];
    const float* bih = (const float*)d_in[9];
    const float* bhh = (const float*)d_in[10];
    const float* qw  = (const float*)d_in[11];
    const float* Wfc = (const float*)d_in[12];
    const float* bfc = (const float*)d_in[13];
    const float* Wout = (const float*)d_in[14];
    const float* bout = (const float*)d_in[15];
    float* out = (float*)d_out;

    prep_kernel<<<24, 256>>>(w0, w1, w2);
    conv_fused_kernel<<<BQ * 4, 256>>>(x, b0, b1, b2);
    recurrent_kernel<0, 128><<<BQ / 8, 256>>>(Wih, Whh, bih, bhh, qw, Wfc, bfc,
                                              Wout, bout, out);
    recurrent_kernel<128, 256><<<BQ / 8, 256>>>(Wih, Whh, bih, bhh, qw, Wfc, bfc,
                                                Wout, bout, out);
}